// round 15
// baseline (speedup 1.0000x reference)
#include <cuda_runtime.h>
#include <cuda_fp16.h>
#include <math.h>
#include <stdint.h>

#define N_NODES 4096
#define IN_F    512
#define NHEAD   8
#define DHEAD   64
#define CTOT    512
#define NB_CAP  128

// Scratch (static device globals — no runtime allocation)
__device__ __align__(16) __half g_mxh[N_NODES * CTOT];   // x @ W fp16 (4 MB)
__device__ __align__(16) __half g_xh [N_NODES * IN_F];   // x fp16 (4 MB)
__device__ __align__(16) __half g_wth[CTOT * IN_F];      // W^T K-major fp16
__device__ __align__(16) float  g_wexp[N_NODES * NHEAD]; // exp weights
__device__ __align__(16) unsigned short g_nbr[N_NODES][NB_CAP]; // CSR (1MB)
__device__ int g_ncnt[N_NODES];

// ---------------- helpers ----------------
__device__ __forceinline__ uint32_t smem_u32(const void* p) {
    return (uint32_t)__cvta_generic_to_shared(p);
}
__device__ __forceinline__ void cpa16(uint32_t saddr, const void* g) {
    asm volatile("cp.async.cg.shared.global [%0], [%1], 16;\n" :: "r"(saddr), "l"(g));
}
// mma m16n8k16 fp16 inputs, fp32 accumulate
__device__ __forceinline__ void mma_f16(float* c, const uint32_t* a, const uint32_t* b) {
    asm volatile(
        "mma.sync.aligned.m16n8k16.row.col.f32.f16.f16.f32 "
        "{%0,%1,%2,%3}, {%4,%5,%6,%7}, {%8,%9}, {%0,%1,%2,%3};"
        : "+f"(c[0]), "+f"(c[1]), "+f"(c[2]), "+f"(c[3])
        : "r"(a[0]), "r"(a[1]), "r"(a[2]), "r"(a[3]), "r"(b[0]), "r"(b[1]));
}

// ---------------------------------------------------------------------------
// Prep (fused, 3 block ranges):
//   [0,4096):        adjacency compaction row i -> CSR g_nbr[i]/g_ncnt[i]
//   [4096,5120):     g_xh = fp16(x)
//   [5120,5184):     W transpose -> g_wth (MLP-4 reads, packed uint4 writes)
// The 64MB adj stream overlaps with the converts; prep was issue=7% idle.
// ---------------------------------------------------------------------------
#define CSEG_CAP 40

__global__ __launch_bounds__(256) void prep_kernel(const float* __restrict__ x,
                                                   const float* __restrict__ W,
                                                   const float* __restrict__ adj)
{
    __shared__ float t[64][65];
    __shared__ unsigned short seg[8][CSEG_CAP];
    __shared__ int cnts[8], offs[8];

    const int b = blockIdx.x;
    if (b < 4096) {
        // ---- compaction: one row per block, 8 warps x 512 cols ----
        const int i    = b;
        const int tid  = threadIdx.x;
        const int warp = tid >> 5;
        const int lane = tid & 31;
        const float* arow = adj + (size_t)i * N_NODES + warp * 512;
        int cnt = 0;
        #pragma unroll
        for (int p = 0; p < 4; p++) {
            int col = p * 128 + lane * 4;
            float4 v = __ldg((const float4*)(arow + col));
            unsigned m4 = (v.x > 0.f ? 1u : 0u) | (v.y > 0.f ? 2u : 0u)
                        | (v.z > 0.f ? 4u : 0u) | (v.w > 0.f ? 8u : 0u);
            int c = __popc(m4), inc = c;
            #pragma unroll
            for (int d2 = 1; d2 < 32; d2 <<= 1) {
                int tt = __shfl_up_sync(0xFFFFFFFFu, inc, d2);
                if (lane >= d2) inc += tt;
            }
            int pos = cnt + inc - c;
            int base = warp * 512 + col;
            #pragma unroll
            for (int bb = 0; bb < 4; bb++)
                if ((m4 >> bb) & 1u) seg[warp][pos++] = (unsigned short)(base + bb);
            cnt += __shfl_sync(0xFFFFFFFFu, inc, 31);
        }
        if (lane == 0) cnts[warp] = cnt;
        __syncthreads();
        if (tid == 0) {
            int s = 0;
            #pragma unroll
            for (int w = 0; w < 8; w++) { offs[w] = s; s += cnts[w]; }
            g_ncnt[i] = s;
        }
        __syncthreads();
        {
            const int o = offs[warp], cw = cnts[warp];
            for (int k = lane; k < cw; k += 32) g_nbr[i][o + k] = seg[warp][k];
        }
    } else if (b < 5120) {
        int i = ((b - 4096) * 256 + threadIdx.x) * 8;
        float4 v0 = __ldg((const float4*)(x + i));
        float4 v1 = __ldg((const float4*)(x + i + 4));
        __half2 h[4];
        h[0] = __floats2half2_rn(v0.x, v0.y);
        h[1] = __floats2half2_rn(v0.z, v0.w);
        h[2] = __floats2half2_rn(v1.x, v1.y);
        h[3] = __floats2half2_rn(v1.z, v1.w);
        *(uint4*)(g_xh + i) = *(uint4*)h;
    } else {
        const int bb = b - 5120;
        const int h  = bb >> 3;
        const int f0 = (bb & 7) * 64;
        const float* Wb = W + (size_t)h * IN_F * DHEAD + (size_t)f0 * DHEAD;
        #pragma unroll
        for (int l = 0; l < 4; l++) {
            int e  = threadIdx.x + l * 256;
            int i  = e >> 4;
            int d4 = (e & 15) * 4;
            float4 v = __ldg((const float4*)(Wb + i * 64 + d4));
            t[i][d4 + 0] = v.x; t[i][d4 + 1] = v.y;
            t[i][d4 + 2] = v.z; t[i][d4 + 3] = v.w;
        }
        __syncthreads();
        const int d  = threadIdx.x >> 2;
        const int i0 = (threadIdx.x & 3) * 16;
        __half hx[16];
        #pragma unroll
        for (int q = 0; q < 16; q++) hx[q] = __float2half_rn(t[i0 + q][d]);
        __half* op = g_wth + (size_t)(h * 64 + d) * IN_F + f0 + i0;
        *(uint4*)(op)     = *(uint4*)(hx);
        *(uint4*)(op + 8) = *(uint4*)(hx + 8);
    }
}

// ---------------------------------------------------------------------------
// Kernel 1 (R14-exact): mx = x @ W via mma.sync m16n8k16 fp16, fp32 accum.
// CTA 64x128 (grid 64x4), 256 threads, 2x4 warps, 32x32 warp tiles, KT=32,
// double-buffered cp.async. Epilogue computes g_wexp = exp(mx . a_dst)
// (a_origin source term cancels in the row softmax).
// ---------------------------------------------------------------------------
#define KT  32
#define NKT (IN_F / KT)   // 16
#define APAD 40           // halves per row (32 data + 8 pad)

__global__ __launch_bounds__(256) void gemm_mx_kernel(const float* __restrict__ a_dst)
{
    __shared__ __align__(16) __half As[2][64][APAD];
    __shared__ __align__(16) __half Bs[2][128][APAD];
    __shared__ float adst_sh[2][64];
    __shared__ float swex[64][2];

    const int tid  = threadIdx.x;
    const int wid  = tid >> 5, lane = tid & 31;
    const int wm   = wid >> 2, wn = wid & 3;
    const int g    = lane >> 2, t4 = lane & 3;
    const int m0   = blockIdx.x * 64;
    const int c0   = blockIdx.y * 128;

    if (tid < 128)
        adst_sh[tid >> 6][tid & 63] =
            __ldg(a_dst + (size_t)(blockIdx.y * 2 + (tid >> 6)) * DHEAD + (tid & 63));

    const uint32_t as_b = smem_u32(&As[0][0][0]);
    const uint32_t bs_b = smem_u32(&Bs[0][0][0]);

    float acc[2][4][4];
    #pragma unroll
    for (int mt = 0; mt < 2; mt++)
        #pragma unroll
        for (int nt = 0; nt < 4; nt++)
            #pragma unroll
            for (int q = 0; q < 4; q++) acc[mt][nt][q] = 0.f;

    const __half* arow = g_xh  + (size_t)m0 * IN_F;
    const __half* brow = g_wth + (size_t)c0 * IN_F;

    auto fill = [&](int s, int t) {
        const int f0 = t * KT;
        {
            int row = tid >> 2, ch = tid & 3;
            uint32_t off = (uint32_t)((s * 64 + row) * (APAD * 2) + ch * 16);
            cpa16(as_b + off, arow + (size_t)row * IN_F + f0 + ch * 8);
        }
        #pragma unroll
        for (int l = 0; l < 2; l++) {
            int idx = tid + l * 256;
            int row = idx >> 2, ch = idx & 3;
            uint32_t off = (uint32_t)((s * 128 + row) * (APAD * 2) + ch * 16);
            cpa16(bs_b + off, brow + (size_t)row * IN_F + f0 + ch * 8);
        }
    };

    fill(0, 0);
    asm volatile("cp.async.commit_group;" ::: "memory");

    for (int t = 0; t < NKT; t++) {
        const int s = t & 1;
        if (t + 1 < NKT) {
            fill(s ^ 1, t + 1);
            asm volatile("cp.async.commit_group;" ::: "memory");
            asm volatile("cp.async.wait_group 1;" ::: "memory");
        } else {
            asm volatile("cp.async.wait_group 0;" ::: "memory");
        }
        __syncthreads();

        #pragma unroll
        for (int ks = 0; ks < 2; ks++) {
            const int kb = ks * 16;
            uint32_t af[2][4];
            #pragma unroll
            for (int mt = 0; mt < 2; mt++) {
                int m = wm * 32 + mt * 16 + g;
                af[mt][0] = *(const uint32_t*)&As[s][m    ][kb + t4 * 2];
                af[mt][1] = *(const uint32_t*)&As[s][m + 8][kb + t4 * 2];
                af[mt][2] = *(const uint32_t*)&As[s][m    ][kb + t4 * 2 + 8];
                af[mt][3] = *(const uint32_t*)&As[s][m + 8][kb + t4 * 2 + 8];
            }
            uint32_t bf[4][2];
            #pragma unroll
            for (int nt = 0; nt < 4; nt++) {
                int n = wn * 32 + nt * 8 + g;
                bf[nt][0] = *(const uint32_t*)&Bs[s][n][kb + t4 * 2];
                bf[nt][1] = *(const uint32_t*)&Bs[s][n][kb + t4 * 2 + 8];
            }
            #pragma unroll
            for (int mt = 0; mt < 2; mt++)
                #pragma unroll
                for (int nt = 0; nt < 4; nt++)
                    mma_f16(acc[mt][nt], af[mt], bf[nt]);
        }
        __syncthreads();
    }

    // ---- epilogue 1: write mxh fp16 ----
    #pragma unroll
    for (int mt = 0; mt < 2; mt++) {
        #pragma unroll
        for (int nt = 0; nt < 4; nt++) {
            int row = m0 + wm * 32 + mt * 16 + g;
            int col = c0 + wn * 32 + nt * 8 + t4 * 2;
            *(__half2*)(g_mxh + (size_t)row * CTOT + col) =
                __floats2half2_rn(acc[mt][nt][0], acc[mt][nt][1]);
            *(__half2*)(g_mxh + (size_t)(row + 8) * CTOT + col) =
                __floats2half2_rn(acc[mt][nt][2], acc[mt][nt][3]);
        }
    }

    // ---- epilogue 2: fused wexp ----
    const int hloc = wn >> 1;
    const int chalf = (wn & 1) * 32;
    float sp[2][2];
    #pragma unroll
    for (int mt = 0; mt < 2; mt++) {
        #pragma unroll
        for (int hi = 0; hi < 2; hi++) {
            float sv = 0.f;
            #pragma unroll
            for (int nt = 0; nt < 4; nt++) {
                int cb = chalf + nt * 8 + t4 * 2;
                sv += acc[mt][nt][hi * 2 + 0] * adst_sh[hloc][cb];
                sv += acc[mt][nt][hi * 2 + 1] * adst_sh[hloc][cb + 1];
            }
            sv += __shfl_xor_sync(0xFFFFFFFFu, sv, 1);
            sv += __shfl_xor_sync(0xFFFFFFFFu, sv, 2);
            sp[mt][hi] = sv;
        }
    }
    if ((wn & 1) == 0 && t4 == 0) {
        #pragma unroll
        for (int mt = 0; mt < 2; mt++)
            #pragma unroll
            for (int hi = 0; hi < 2; hi++)
                swex[wm * 32 + mt * 16 + hi * 8 + g][hloc] = sp[mt][hi];
    }
    __syncthreads();
    if ((wn & 1) == 1 && t4 == 0) {
        #pragma unroll
        for (int mt = 0; mt < 2; mt++)
            #pragma unroll
            for (int hi = 0; hi < 2; hi++) {
                int r = wm * 32 + mt * 16 + hi * 8 + g;
                float tot = swex[r][hloc] + sp[mt][hi];
                g_wexp[(size_t)(m0 + r) * NHEAD + blockIdx.y * 2 + hloc] = expf(tot);
            }
    }
}

// ---------------------------------------------------------------------------
// Kernel 2 (gather): out[i,c] = sum_j w[j,h] mx[j,c] / sum_j w[j,h]
// Reads CSR built in prep. 128 thr/block, one block per row.
// Thread owns 4 channels (uint2 loads), walks ALL neighbors, unroll-8
// (8 outstanding 8B loads/thread), fp32 accumulation, no partial reduce.
// ---------------------------------------------------------------------------
__global__ __launch_bounds__(128) void gather_kernel(float* __restrict__ out)
{
    __shared__ unsigned short ulist[NB_CAP];
    __shared__ __align__(16) float wsh[NB_CAP][NHEAD];

    const int i   = blockIdx.x;
    const int tid = threadIdx.x;
    const int nb  = __ldg(g_ncnt + i);

    if (tid < nb) ulist[tid] = g_nbr[i][tid];
    __syncthreads();
    for (int idx = tid; idx < nb * 2; idx += 128) {
        int k = idx >> 1, hf = idx & 1;
        *(float4*)&wsh[k][hf * 4] =
            __ldg((const float4*)(g_wexp + (size_t)ulist[k] * NHEAD + hf * 4));
    }
    __syncthreads();

    const int h = tid >> 4;                       // head = (tid*4)/64
    const __half* base = g_mxh + tid * 4;

    float a0 = 0.f, a1 = 0.f, a2 = 0.f, a3 = 0.f, den = 0.f;
    int k = 0;
    for (; k + 8 <= nb; k += 8) {
        uint2 r[8];
        int j[8];
        #pragma unroll
        for (int u = 0; u < 8; u++) j[u] = ulist[k + u];
        #pragma unroll
        for (int u = 0; u < 8; u++)
            r[u] = __ldg((const uint2*)(base + (size_t)j[u] * CTOT));
        #pragma unroll
        for (int u = 0; u < 8; u++) {
            float w = wsh[k + u][h];
            float2 f0 = __half22float2(*(__half2*)&r[u].x);
            float2 f1 = __half22float2(*(__half2*)&r[u].y);
            a0 += f0.x * w; a1 += f0.y * w;
            a2 += f1.x * w; a3 += f1.y * w;
            den += w;
        }
    }
    for (; k < nb; k++) {
        int j0 = ulist[k];
        uint2 r0 = __ldg((const uint2*)(base + (size_t)j0 * CTOT));
        float w = wsh[k][h];
        float2 f0 = __half22float2(*(__half2*)&r0.x);
        float2 f1 = __half22float2(*(__half2*)&r0.y);
        a0 += f0.x * w; a1 += f0.y * w;
        a2 += f1.x * w; a3 += f1.y * w;
        den += w;
    }

    float inv = 1.f / den;
    *(float4*)(out + (size_t)i * CTOT + tid * 4) =
        make_float4(a0 * inv, a1 * inv, a2 * inv, a3 * inv);
}

// ---------------------------------------------------------------------------
// Inputs: x[4096,512], adj[4096,4096], W[8,512,64], a_origin[8,64] (cancels),
//         a_dst[8,64].  Output: float32 [4096, 512]
// ---------------------------------------------------------------------------
extern "C" void kernel_launch(void* const* d_in, const int* in_sizes, int n_in,
                              void* d_out, int out_size)
{
    const float* x     = (const float*)d_in[0];
    const float* adj   = (const float*)d_in[1];
    const float* W     = (const float*)d_in[2];
    const float* a_dst = (const float*)d_in[4];
    float* out = (float*)d_out;

    prep_kernel<<<5184, 256>>>(x, W, adj);
    gemm_mx_kernel<<<dim3(64, 4), 256>>>(a_dst);
    gather_kernel<<<N_NODES, 128>>>(out);
}

// round 16
// speedup vs baseline: 1.0343x; 1.0343x over previous
#include <cuda_runtime.h>
#include <cuda_fp16.h>
#include <math.h>
#include <stdint.h>

#define N_NODES 4096
#define IN_F    512
#define NHEAD   8
#define DHEAD   64
#define CTOT    512
#define NB_CAP  128

// Scratch (static device globals — no runtime allocation)
__device__ __align__(16) __half g_mxh[N_NODES * CTOT];   // x @ W fp16 (4 MB)
__device__ __align__(16) __half g_xh [N_NODES * IN_F];   // x fp16 (4 MB)
__device__ __align__(16) __half g_wth[CTOT * IN_F];      // W^T K-major fp16
__device__ __align__(16) float  g_wexp[N_NODES * NHEAD]; // exp weights

// ---------------- helpers ----------------
__device__ __forceinline__ uint32_t smem_u32(const void* p) {
    return (uint32_t)__cvta_generic_to_shared(p);
}
__device__ __forceinline__ void cpa16(uint32_t saddr, const void* g) {
    asm volatile("cp.async.cg.shared.global [%0], [%1], 16;\n" :: "r"(saddr), "l"(g));
}
// mma m16n8k16 fp16 inputs, fp32 accumulate
__device__ __forceinline__ void mma_f16(float* c, const uint32_t* a, const uint32_t* b) {
    asm volatile(
        "mma.sync.aligned.m16n8k16.row.col.f32.f16.f16.f32 "
        "{%0,%1,%2,%3}, {%4,%5,%6,%7}, {%8,%9}, {%0,%1,%2,%3};"
        : "+f"(c[0]), "+f"(c[1]), "+f"(c[2]), "+f"(c[3])
        : "r"(a[0]), "r"(a[1]), "r"(a[2]), "r"(a[3]), "r"(b[0]), "r"(b[1]));
}

// ---------------------------------------------------------------------------
// Prep (fused): blocks [0,512): g_xh = fp16(x), 16 floats/thread (MLP 4).
//               blocks [512,576): W transpose (MLP-4 reads, uint4 writes).
// ---------------------------------------------------------------------------
__global__ __launch_bounds__(256) void prep_kernel(const float* __restrict__ x,
                                                   const float* __restrict__ W)
{
    if (blockIdx.x < 512) {
        int i = (blockIdx.x * 256 + threadIdx.x) * 16;
        float4 v0 = __ldg((const float4*)(x + i));
        float4 v1 = __ldg((const float4*)(x + i + 4));
        float4 v2 = __ldg((const float4*)(x + i + 8));
        float4 v3 = __ldg((const float4*)(x + i + 12));
        __half2 h[8];
        h[0] = __floats2half2_rn(v0.x, v0.y);
        h[1] = __floats2half2_rn(v0.z, v0.w);
        h[2] = __floats2half2_rn(v1.x, v1.y);
        h[3] = __floats2half2_rn(v1.z, v1.w);
        h[4] = __floats2half2_rn(v2.x, v2.y);
        h[5] = __floats2half2_rn(v2.z, v2.w);
        h[6] = __floats2half2_rn(v3.x, v3.y);
        h[7] = __floats2half2_rn(v3.z, v3.w);
        *(uint4*)(g_xh + i)     = *(uint4*)(h);
        *(uint4*)(g_xh + i + 8) = *(uint4*)(h + 4);
    } else {
        __shared__ float t[64][65];
        const int b  = blockIdx.x - 512;
        const int h  = b >> 3;
        const int f0 = (b & 7) * 64;
        const float* Wb = W + (size_t)h * IN_F * DHEAD + (size_t)f0 * DHEAD;
        #pragma unroll
        for (int l = 0; l < 4; l++) {
            int e  = threadIdx.x + l * 256;
            int i  = e >> 4;
            int d4 = (e & 15) * 4;
            float4 v = __ldg((const float4*)(Wb + i * 64 + d4));
            t[i][d4 + 0] = v.x; t[i][d4 + 1] = v.y;
            t[i][d4 + 2] = v.z; t[i][d4 + 3] = v.w;
        }
        __syncthreads();
        const int d  = threadIdx.x >> 2;
        const int i0 = (threadIdx.x & 3) * 16;
        __half hx[16];
        #pragma unroll
        for (int q = 0; q < 16; q++) hx[q] = __float2half_rn(t[i0 + q][d]);
        __half* op = g_wth + (size_t)(h * 64 + d) * IN_F + f0 + i0;
        *(uint4*)(op)     = *(uint4*)(hx);
        *(uint4*)(op + 8) = *(uint4*)(hx + 8);
    }
}

// ---------------------------------------------------------------------------
// Kernel 1 (R14-exact): mx = x @ W via mma.sync m16n8k16 fp16, fp32 accum.
// CTA 64x128 (grid 64x4), 256 threads, 2x4 warps, 32x32 warp tiles, KT=32,
// double-buffered cp.async. Epilogue computes g_wexp = exp(mx . a_dst)
// (a_origin source term cancels in the row softmax).
// ---------------------------------------------------------------------------
#define KT  32
#define NKT (IN_F / KT)   // 16
#define APAD 40           // halves per row (32 data + 8 pad)

__global__ __launch_bounds__(256) void gemm_mx_kernel(const float* __restrict__ a_dst)
{
    __shared__ __align__(16) __half As[2][64][APAD];
    __shared__ __align__(16) __half Bs[2][128][APAD];
    __shared__ float adst_sh[2][64];
    __shared__ float swex[64][2];

    const int tid  = threadIdx.x;
    const int wid  = tid >> 5, lane = tid & 31;
    const int wm   = wid >> 2, wn = wid & 3;
    const int g    = lane >> 2, t4 = lane & 3;
    const int m0   = blockIdx.x * 64;
    const int c0   = blockIdx.y * 128;

    if (tid < 128)
        adst_sh[tid >> 6][tid & 63] =
            __ldg(a_dst + (size_t)(blockIdx.y * 2 + (tid >> 6)) * DHEAD + (tid & 63));

    const uint32_t as_b = smem_u32(&As[0][0][0]);
    const uint32_t bs_b = smem_u32(&Bs[0][0][0]);

    float acc[2][4][4];
    #pragma unroll
    for (int mt = 0; mt < 2; mt++)
        #pragma unroll
        for (int nt = 0; nt < 4; nt++)
            #pragma unroll
            for (int q = 0; q < 4; q++) acc[mt][nt][q] = 0.f;

    const __half* arow = g_xh  + (size_t)m0 * IN_F;
    const __half* brow = g_wth + (size_t)c0 * IN_F;

    auto fill = [&](int s, int t) {
        const int f0 = t * KT;
        {
            int row = tid >> 2, ch = tid & 3;
            uint32_t off = (uint32_t)((s * 64 + row) * (APAD * 2) + ch * 16);
            cpa16(as_b + off, arow + (size_t)row * IN_F + f0 + ch * 8);
        }
        #pragma unroll
        for (int l = 0; l < 2; l++) {
            int idx = tid + l * 256;
            int row = idx >> 2, ch = idx & 3;
            uint32_t off = (uint32_t)((s * 128 + row) * (APAD * 2) + ch * 16);
            cpa16(bs_b + off, brow + (size_t)row * IN_F + f0 + ch * 8);
        }
    };

    fill(0, 0);
    asm volatile("cp.async.commit_group;" ::: "memory");

    for (int t = 0; t < NKT; t++) {
        const int s = t & 1;
        if (t + 1 < NKT) {
            fill(s ^ 1, t + 1);
            asm volatile("cp.async.commit_group;" ::: "memory");
            asm volatile("cp.async.wait_group 1;" ::: "memory");
        } else {
            asm volatile("cp.async.wait_group 0;" ::: "memory");
        }
        __syncthreads();

        #pragma unroll
        for (int ks = 0; ks < 2; ks++) {
            const int kb = ks * 16;
            uint32_t af[2][4];
            #pragma unroll
            for (int mt = 0; mt < 2; mt++) {
                int m = wm * 32 + mt * 16 + g;
                af[mt][0] = *(const uint32_t*)&As[s][m    ][kb + t4 * 2];
                af[mt][1] = *(const uint32_t*)&As[s][m + 8][kb + t4 * 2];
                af[mt][2] = *(const uint32_t*)&As[s][m    ][kb + t4 * 2 + 8];
                af[mt][3] = *(const uint32_t*)&As[s][m + 8][kb + t4 * 2 + 8];
            }
            uint32_t bf[4][2];
            #pragma unroll
            for (int nt = 0; nt < 4; nt++) {
                int n = wn * 32 + nt * 8 + g;
                bf[nt][0] = *(const uint32_t*)&Bs[s][n][kb + t4 * 2];
                bf[nt][1] = *(const uint32_t*)&Bs[s][n][kb + t4 * 2 + 8];
            }
            #pragma unroll
            for (int mt = 0; mt < 2; mt++)
                #pragma unroll
                for (int nt = 0; nt < 4; nt++)
                    mma_f16(acc[mt][nt], af[mt], bf[nt]);
        }
        __syncthreads();
    }

    // ---- epilogue 1: write mxh fp16 ----
    #pragma unroll
    for (int mt = 0; mt < 2; mt++) {
        #pragma unroll
        for (int nt = 0; nt < 4; nt++) {
            int row = m0 + wm * 32 + mt * 16 + g;
            int col = c0 + wn * 32 + nt * 8 + t4 * 2;
            *(__half2*)(g_mxh + (size_t)row * CTOT + col) =
                __floats2half2_rn(acc[mt][nt][0], acc[mt][nt][1]);
            *(__half2*)(g_mxh + (size_t)(row + 8) * CTOT + col) =
                __floats2half2_rn(acc[mt][nt][2], acc[mt][nt][3]);
        }
    }

    // ---- epilogue 2: fused wexp ----
    const int hloc = wn >> 1;
    const int chalf = (wn & 1) * 32;
    float sp[2][2];
    #pragma unroll
    for (int mt = 0; mt < 2; mt++) {
        #pragma unroll
        for (int hi = 0; hi < 2; hi++) {
            float sv = 0.f;
            #pragma unroll
            for (int nt = 0; nt < 4; nt++) {
                int cb = chalf + nt * 8 + t4 * 2;
                sv += acc[mt][nt][hi * 2 + 0] * adst_sh[hloc][cb];
                sv += acc[mt][nt][hi * 2 + 1] * adst_sh[hloc][cb + 1];
            }
            sv += __shfl_xor_sync(0xFFFFFFFFu, sv, 1);
            sv += __shfl_xor_sync(0xFFFFFFFFu, sv, 2);
            sp[mt][hi] = sv;
        }
    }
    if ((wn & 1) == 0 && t4 == 0) {
        #pragma unroll
        for (int mt = 0; mt < 2; mt++)
            #pragma unroll
            for (int hi = 0; hi < 2; hi++)
                swex[wm * 32 + mt * 16 + hi * 8 + g][hloc] = sp[mt][hi];
    }
    __syncthreads();
    if ((wn & 1) == 1 && t4 == 0) {
        #pragma unroll
        for (int mt = 0; mt < 2; mt++)
            #pragma unroll
            for (int hi = 0; hi < 2; hi++) {
                int r = wm * 32 + mt * 16 + hi * 8 + g;
                float tot = swex[r][hloc] + sp[mt][hi];
                g_wexp[(size_t)(m0 + r) * NHEAD + blockIdx.y * 2 + hloc] = expf(tot);
            }
    }
}

// ---------------------------------------------------------------------------
// Kernel 2: out[i,c] = sum_{j in adj(i)} w[j,h] mx[j,c] / sum_j w[j,h]
// One block (128 thr) per row.
// Phase A: cp.async-stage the 16KB adj row into smem (1024 x 16B in flight,
//          no register cost), then ordered ballot-scan from LDS.
// Phase B: R6 fp32 gather body (measured best).
// ---------------------------------------------------------------------------
#define SEG_CAP 96

__device__ __forceinline__ void acc8(float* acc, uint4 r, float w) {
    float2 f0 = __half22float2(*(__half2*)&r.x);
    float2 f1 = __half22float2(*(__half2*)&r.y);
    float2 f2 = __half22float2(*(__half2*)&r.z);
    float2 f3 = __half22float2(*(__half2*)&r.w);
    acc[0] += f0.x * w; acc[1] += f0.y * w;
    acc[2] += f1.x * w; acc[3] += f1.y * w;
    acc[4] += f2.x * w; acc[5] += f2.y * w;
    acc[6] += f3.x * w; acc[7] += f3.y * w;
}

__global__ __launch_bounds__(128) void aggregate_kernel(
    const float* __restrict__ adj, float* __restrict__ out)
{
    __shared__ __align__(16) float adjsh[N_NODES];     // 16 KB
    __shared__ unsigned short seg[4][SEG_CAP];
    __shared__ int cnts[4], nb_sh;
    __shared__ int offs[4];
    __shared__ unsigned short ulist[NB_CAP];
    __shared__ __align__(16) float wsh[NB_CAP][NHEAD];
    __shared__ __align__(16) float pac[64][9];
    __shared__ float pden1[64];

    const int i    = blockIdx.x;
    const int tid  = threadIdx.x;
    const int warp = tid >> 5;
    const int lane = tid & 31;

    // ---- stage adj row into smem: 8 x 16B cp.async per thread, one wait ----
    {
        const float* arow = adj + (size_t)i * N_NODES;
        const uint32_t ab = smem_u32(adjsh);
        #pragma unroll
        for (int l = 0; l < 8; l++) {
            int e = tid + l * 128;            // float4 index 0..1023
            cpa16(ab + e * 16, arow + e * 4);
        }
        asm volatile("cp.async.commit_group;" ::: "memory");
        asm volatile("cp.async.wait_group 0;" ::: "memory");
        __syncthreads();
    }

    // ---- Phase A: ordered compaction from smem ----
    {
        const float* as = adjsh + warp * 1024;
        int cnt = 0;
        #pragma unroll
        for (int p = 0; p < 8; p++) {
            int col = p * 128 + lane * 4;
            float4 v = *(const float4*)(as + col);
            unsigned m4 = (v.x > 0.f ? 1u : 0u) | (v.y > 0.f ? 2u : 0u)
                        | (v.z > 0.f ? 4u : 0u) | (v.w > 0.f ? 8u : 0u);
            int c = __popc(m4), inc = c;
            #pragma unroll
            for (int d2 = 1; d2 < 32; d2 <<= 1) {
                int t = __shfl_up_sync(0xFFFFFFFFu, inc, d2);
                if (lane >= d2) inc += t;
            }
            int pos = cnt + inc - c;
            int base = warp * 1024 + col;
            #pragma unroll
            for (int b = 0; b < 4; b++)
                if ((m4 >> b) & 1u) seg[warp][pos++] = (unsigned short)(base + b);
            cnt += __shfl_sync(0xFFFFFFFFu, inc, 31);
        }
        if (lane == 0) cnts[warp] = cnt;
    }
    __syncthreads();
    if (tid == 0) {
        int s = 0;
        #pragma unroll
        for (int w = 0; w < 4; w++) { offs[w] = s; s += cnts[w]; }
        nb_sh = s;
    }
    __syncthreads();
    {
        const int o = offs[warp], cw = cnts[warp];
        for (int k = lane; k < cw; k += 32) ulist[o + k] = seg[warp][k];
        for (int idx = lane; idx < cw * 2; idx += 32) {
            int k = idx >> 1, hf = idx & 1;
            *(float4*)&wsh[o + k][hf * 4] =
                __ldg((const float4*)(g_wexp + (size_t)seg[warp][k] * NHEAD + hf * 4));
        }
    }
    __syncthreads();

    // ---- Phase B (R6): fp32 gather ----
    const int nb  = nb_sh;
    const int cg  = tid & 63;
    const int sub = tid >> 6;
    const int h   = cg >> 3;
    const __half* base = g_mxh + cg * 8;

    float acc[8] = {0.f, 0.f, 0.f, 0.f, 0.f, 0.f, 0.f, 0.f};
    float den = 0.f;
    int k = sub;
    for (; k + 6 < nb; k += 8) {
        int j0 = ulist[k], j1 = ulist[k + 2], j2 = ulist[k + 4], j3 = ulist[k + 6];
        uint4 r0 = __ldg((const uint4*)(base + (size_t)j0 * CTOT));
        uint4 r1 = __ldg((const uint4*)(base + (size_t)j1 * CTOT));
        uint4 r2 = __ldg((const uint4*)(base + (size_t)j2 * CTOT));
        uint4 r3 = __ldg((const uint4*)(base + (size_t)j3 * CTOT));
        float w0 = wsh[k][h], w1 = wsh[k + 2][h], w2 = wsh[k + 4][h], w3 = wsh[k + 6][h];
        acc8(acc, r0, w0); acc8(acc, r1, w1); acc8(acc, r2, w2); acc8(acc, r3, w3);
        den += w0; den += w1; den += w2; den += w3;
    }
    for (; k < nb; k += 2) {
        int j0 = ulist[k];
        uint4 r0 = __ldg((const uint4*)(base + (size_t)j0 * CTOT));
        float w0 = wsh[k][h];
        acc8(acc, r0, w0);
        den += w0;
    }

    if (sub == 1) {
        #pragma unroll
        for (int q = 0; q < 8; q++) pac[cg][q] = acc[q];
        pden1[cg] = den;
    }
    __syncthreads();
    if (sub == 0) {
        den += pden1[cg];
        float inv = 1.f / den;
        float* op = out + (size_t)i * CTOT + cg * 8;
        *(float4*)(op) = make_float4((acc[0] + pac[cg][0]) * inv,
                                     (acc[1] + pac[cg][1]) * inv,
                                     (acc[2] + pac[cg][2]) * inv,
                                     (acc[3] + pac[cg][3]) * inv);
        *(float4*)(op + 4) = make_float4((acc[4] + pac[cg][4]) * inv,
                                         (acc[5] + pac[cg][5]) * inv,
                                         (acc[6] + pac[cg][6]) * inv,
                                         (acc[7] + pac[cg][7]) * inv);
    }
}

// ---------------------------------------------------------------------------
// Inputs: x[4096,512], adj[4096,4096], W[8,512,64], a_origin[8,64] (cancels),
//         a_dst[8,64].  Output: float32 [4096, 512]
// ---------------------------------------------------------------------------
extern "C" void kernel_launch(void* const* d_in, const int* in_sizes, int n_in,
                              void* d_out, int out_size)
{
    const float* x     = (const float*)d_in[0];
    const float* adj   = (const float*)d_in[1];
    const float* W     = (const float*)d_in[2];
    const float* a_dst = (const float*)d_in[4];
    float* out = (float*)d_out;

    prep_kernel<<<576, 256>>>(x, W);
    gemm_mx_kernel<<<dim3(64, 4), 256>>>(a_dst);
    aggregate_kernel<<<N_NODES, 128>>>(adj, out);
}

// round 17
// speedup vs baseline: 1.1794x; 1.1403x over previous
#include <cuda_runtime.h>
#include <cuda_fp16.h>
#include <math.h>
#include <stdint.h>

#define N_NODES 4096
#define IN_F    512
#define NHEAD   8
#define DHEAD   64
#define CTOT    512
#define NB_CAP  128

// Scratch (static device globals — no runtime allocation)
__device__ __align__(16) __half g_mxh[N_NODES * CTOT];   // x @ W fp16 (4 MB)
__device__ __align__(16) __half g_xh [N_NODES * IN_F];   // x fp16 (4 MB)
__device__ __align__(16) __half g_wth[CTOT * IN_F];      // W^T K-major fp16
__device__ __align__(16) float  g_wexp[N_NODES * NHEAD]; // exp weights

// ---------------- helpers ----------------
__device__ __forceinline__ uint32_t smem_u32(const void* p) {
    return (uint32_t)__cvta_generic_to_shared(p);
}
__device__ __forceinline__ void cpa16(uint32_t saddr, const void* g) {
    asm volatile("cp.async.cg.shared.global [%0], [%1], 16;\n" :: "r"(saddr), "l"(g));
}
// mma m16n8k16 fp16 inputs, fp32 accumulate
__device__ __forceinline__ void mma_f16(float* c, const uint32_t* a, const uint32_t* b) {
    asm volatile(
        "mma.sync.aligned.m16n8k16.row.col.f32.f16.f16.f32 "
        "{%0,%1,%2,%3}, {%4,%5,%6,%7}, {%8,%9}, {%0,%1,%2,%3};"
        : "+f"(c[0]), "+f"(c[1]), "+f"(c[2]), "+f"(c[3])
        : "r"(a[0]), "r"(a[1]), "r"(a[2]), "r"(a[3]), "r"(b[0]), "r"(b[1]));
}

// ---------------------------------------------------------------------------
// Prep (R14-exact): blocks [0,1024): g_xh = fp16(x), 8 floats/thread.
//                   blocks [1024,1088): W transpose (MLP-4, uint4 writes).
// ---------------------------------------------------------------------------
__global__ __launch_bounds__(256) void prep_kernel(const float* __restrict__ x,
                                                   const float* __restrict__ W)
{
    if (blockIdx.x < 1024) {
        int i = (blockIdx.x * 256 + threadIdx.x) * 8;
        float4 v0 = __ldg((const float4*)(x + i));
        float4 v1 = __ldg((const float4*)(x + i + 4));
        __half2 h[4];
        h[0] = __floats2half2_rn(v0.x, v0.y);
        h[1] = __floats2half2_rn(v0.z, v0.w);
        h[2] = __floats2half2_rn(v1.x, v1.y);
        h[3] = __floats2half2_rn(v1.z, v1.w);
        *(uint4*)(g_xh + i) = *(uint4*)h;
    } else {
        __shared__ float t[64][65];
        const int b  = blockIdx.x - 1024;
        const int h  = b >> 3;
        const int f0 = (b & 7) * 64;
        const float* Wb = W + (size_t)h * IN_F * DHEAD + (size_t)f0 * DHEAD;
        #pragma unroll
        for (int l = 0; l < 4; l++) {
            int e  = threadIdx.x + l * 256;
            int i  = e >> 4;
            int d4 = (e & 15) * 4;
            float4 v = __ldg((const float4*)(Wb + i * 64 + d4));
            t[i][d4 + 0] = v.x; t[i][d4 + 1] = v.y;
            t[i][d4 + 2] = v.z; t[i][d4 + 3] = v.w;
        }
        __syncthreads();
        const int d  = threadIdx.x >> 2;
        const int i0 = (threadIdx.x & 3) * 16;
        __half hx[16];
        #pragma unroll
        for (int q = 0; q < 16; q++) hx[q] = __float2half_rn(t[i0 + q][d]);
        __half* op = g_wth + (size_t)(h * 64 + d) * IN_F + f0 + i0;
        *(uint4*)(op)     = *(uint4*)(hx);
        *(uint4*)(op + 8) = *(uint4*)(hx + 8);
    }
}

// ---------------------------------------------------------------------------
// Kernel 1 (R14-exact): mx = x @ W via mma.sync m16n8k16 fp16, fp32 accum.
// CTA 64x128 (grid 64x4), 256 threads, 2x4 warps, 32x32 warp tiles, KT=32,
// double-buffered cp.async. Epilogue computes g_wexp = exp(mx . a_dst)
// (a_origin source term cancels in the row softmax).
// ---------------------------------------------------------------------------
#define KT  32
#define NKT (IN_F / KT)   // 16
#define APAD 40           // halves per row (32 data + 8 pad)

__global__ __launch_bounds__(256) void gemm_mx_kernel(const float* __restrict__ a_dst)
{
    __shared__ __align__(16) __half As[2][64][APAD];
    __shared__ __align__(16) __half Bs[2][128][APAD];
    __shared__ float adst_sh[2][64];
    __shared__ float swex[64][2];

    const int tid  = threadIdx.x;
    const int wid  = tid >> 5, lane = tid & 31;
    const int wm   = wid >> 2, wn = wid & 3;
    const int g    = lane >> 2, t4 = lane & 3;
    const int m0   = blockIdx.x * 64;
    const int c0   = blockIdx.y * 128;

    if (tid < 128)
        adst_sh[tid >> 6][tid & 63] =
            __ldg(a_dst + (size_t)(blockIdx.y * 2 + (tid >> 6)) * DHEAD + (tid & 63));

    const uint32_t as_b = smem_u32(&As[0][0][0]);
    const uint32_t bs_b = smem_u32(&Bs[0][0][0]);

    float acc[2][4][4];
    #pragma unroll
    for (int mt = 0; mt < 2; mt++)
        #pragma unroll
        for (int nt = 0; nt < 4; nt++)
            #pragma unroll
            for (int q = 0; q < 4; q++) acc[mt][nt][q] = 0.f;

    const __half* arow = g_xh  + (size_t)m0 * IN_F;
    const __half* brow = g_wth + (size_t)c0 * IN_F;

    auto fill = [&](int s, int t) {
        const int f0 = t * KT;
        {
            int row = tid >> 2, ch = tid & 3;
            uint32_t off = (uint32_t)((s * 64 + row) * (APAD * 2) + ch * 16);
            cpa16(as_b + off, arow + (size_t)row * IN_F + f0 + ch * 8);
        }
        #pragma unroll
        for (int l = 0; l < 2; l++) {
            int idx = tid + l * 256;
            int row = idx >> 2, ch = idx & 3;
            uint32_t off = (uint32_t)((s * 128 + row) * (APAD * 2) + ch * 16);
            cpa16(bs_b + off, brow + (size_t)row * IN_F + f0 + ch * 8);
        }
    };

    fill(0, 0);
    asm volatile("cp.async.commit_group;" ::: "memory");

    for (int t = 0; t < NKT; t++) {
        const int s = t & 1;
        if (t + 1 < NKT) {
            fill(s ^ 1, t + 1);
            asm volatile("cp.async.commit_group;" ::: "memory");
            asm volatile("cp.async.wait_group 1;" ::: "memory");
        } else {
            asm volatile("cp.async.wait_group 0;" ::: "memory");
        }
        __syncthreads();

        #pragma unroll
        for (int ks = 0; ks < 2; ks++) {
            const int kb = ks * 16;
            uint32_t af[2][4];
            #pragma unroll
            for (int mt = 0; mt < 2; mt++) {
                int m = wm * 32 + mt * 16 + g;
                af[mt][0] = *(const uint32_t*)&As[s][m    ][kb + t4 * 2];
                af[mt][1] = *(const uint32_t*)&As[s][m + 8][kb + t4 * 2];
                af[mt][2] = *(const uint32_t*)&As[s][m    ][kb + t4 * 2 + 8];
                af[mt][3] = *(const uint32_t*)&As[s][m + 8][kb + t4 * 2 + 8];
            }
            uint32_t bf[4][2];
            #pragma unroll
            for (int nt = 0; nt < 4; nt++) {
                int n = wn * 32 + nt * 8 + g;
                bf[nt][0] = *(const uint32_t*)&Bs[s][n][kb + t4 * 2];
                bf[nt][1] = *(const uint32_t*)&Bs[s][n][kb + t4 * 2 + 8];
            }
            #pragma unroll
            for (int mt = 0; mt < 2; mt++)
                #pragma unroll
                for (int nt = 0; nt < 4; nt++)
                    mma_f16(acc[mt][nt], af[mt], bf[nt]);
        }
        __syncthreads();
    }

    // ---- epilogue 1: write mxh fp16 ----
    #pragma unroll
    for (int mt = 0; mt < 2; mt++) {
        #pragma unroll
        for (int nt = 0; nt < 4; nt++) {
            int row = m0 + wm * 32 + mt * 16 + g;
            int col = c0 + wn * 32 + nt * 8 + t4 * 2;
            *(__half2*)(g_mxh + (size_t)row * CTOT + col) =
                __floats2half2_rn(acc[mt][nt][0], acc[mt][nt][1]);
            *(__half2*)(g_mxh + (size_t)(row + 8) * CTOT + col) =
                __floats2half2_rn(acc[mt][nt][2], acc[mt][nt][3]);
        }
    }

    // ---- epilogue 2: fused wexp ----
    const int hloc = wn >> 1;
    const int chalf = (wn & 1) * 32;
    float sp[2][2];
    #pragma unroll
    for (int mt = 0; mt < 2; mt++) {
        #pragma unroll
        for (int hi = 0; hi < 2; hi++) {
            float sv = 0.f;
            #pragma unroll
            for (int nt = 0; nt < 4; nt++) {
                int cb = chalf + nt * 8 + t4 * 2;
                sv += acc[mt][nt][hi * 2 + 0] * adst_sh[hloc][cb];
                sv += acc[mt][nt][hi * 2 + 1] * adst_sh[hloc][cb + 1];
            }
            sv += __shfl_xor_sync(0xFFFFFFFFu, sv, 1);
            sv += __shfl_xor_sync(0xFFFFFFFFu, sv, 2);
            sp[mt][hi] = sv;
        }
    }
    if ((wn & 1) == 0 && t4 == 0) {
        #pragma unroll
        for (int mt = 0; mt < 2; mt++)
            #pragma unroll
            for (int hi = 0; hi < 2; hi++)
                swex[wm * 32 + mt * 16 + hi * 8 + g][hloc] = sp[mt][hi];
    }
    __syncthreads();
    if ((wn & 1) == 1 && t4 == 0) {
        #pragma unroll
        for (int mt = 0; mt < 2; mt++)
            #pragma unroll
            for (int hi = 0; hi < 2; hi++) {
                int r = wm * 32 + mt * 16 + hi * 8 + g;
                float tot = swex[r][hloc] + sp[mt][hi];
                g_wexp[(size_t)(m0 + r) * NHEAD + blockIdx.y * 2 + hloc] = expf(tot);
            }
    }
}

// ---------------------------------------------------------------------------
// Kernel 2: out[i,c] = sum_{j in adj(i)} w[j,h] mx[j,c] / sum_j w[j,h]
// One block (128 thr) per row.
// Phase A v2: 8 coalesced float4 loads per lane (lane-interleaved layout,
//   MLP 8) -> one 32-bit mask -> ONE warp scan -> fixed-order bit pop.
//   (deterministic order; not sorted -- summation order is fixed per launch)
// Phase B: R6/R14 fp32 gather body (measured best).
// ---------------------------------------------------------------------------
#define SEG_CAP 96

__device__ __forceinline__ void acc8(float* acc, uint4 r, float w) {
    float2 f0 = __half22float2(*(__half2*)&r.x);
    float2 f1 = __half22float2(*(__half2*)&r.y);
    float2 f2 = __half22float2(*(__half2*)&r.z);
    float2 f3 = __half22float2(*(__half2*)&r.w);
    acc[0] += f0.x * w; acc[1] += f0.y * w;
    acc[2] += f1.x * w; acc[3] += f1.y * w;
    acc[4] += f2.x * w; acc[5] += f2.y * w;
    acc[6] += f3.x * w; acc[7] += f3.y * w;
}

__global__ __launch_bounds__(128) void aggregate_kernel(
    const float* __restrict__ adj, float* __restrict__ out)
{
    __shared__ unsigned short seg[4][SEG_CAP];
    __shared__ int cnts[4], nb_sh;
    __shared__ int offs[4];
    __shared__ unsigned short ulist[NB_CAP];
    __shared__ __align__(16) float wsh[NB_CAP][NHEAD];
    __shared__ __align__(16) float pac[64][9];
    __shared__ float pden1[64];

    const int i    = blockIdx.x;
    const int tid  = threadIdx.x;
    const int warp = tid >> 5;
    const int lane = tid & 31;

    // ---- Phase A v2: mask build (8 coalesced loads) + single scan ----
    {
        const float* arow = adj + (size_t)i * N_NODES + warp * 1024 + lane * 4;
        unsigned mask = 0u;
        #pragma unroll
        for (int p = 0; p < 8; p++) {
            float4 v = __ldg((const float4*)(arow + p * 128));
            unsigned m4 = (v.x > 0.f ? 1u : 0u) | (v.y > 0.f ? 2u : 0u)
                        | (v.z > 0.f ? 4u : 0u) | (v.w > 0.f ? 8u : 0u);
            mask |= m4 << (p * 4);
        }
        int c = __popc(mask), inc = c;
        #pragma unroll
        for (int d2 = 1; d2 < 32; d2 <<= 1) {
            int t = __shfl_up_sync(0xFFFFFFFFu, inc, d2);
            if (lane >= d2) inc += t;
        }
        int pos = inc - c;
        const int lbase = warp * 1024 + lane * 4;
        while (mask) {
            int q = __ffs(mask) - 1;        // bit q = chunk(q>>2), elem(q&3)
            seg[warp][pos++] = (unsigned short)(lbase + (q >> 2) * 128 + (q & 3));
            mask &= mask - 1;
        }
        if (lane == 31) cnts[warp] = inc;
    }
    __syncthreads();
    if (tid == 0) {
        int s = 0;
        #pragma unroll
        for (int w = 0; w < 4; w++) { offs[w] = s; s += cnts[w]; }
        nb_sh = s;
    }
    __syncthreads();
    {
        const int o = offs[warp], cw = cnts[warp];
        for (int k = lane; k < cw; k += 32) ulist[o + k] = seg[warp][k];
        for (int idx = lane; idx < cw * 2; idx += 32) {
            int k = idx >> 1, hf = idx & 1;
            *(float4*)&wsh[o + k][hf * 4] =
                __ldg((const float4*)(g_wexp + (size_t)seg[warp][k] * NHEAD + hf * 4));
        }
    }
    __syncthreads();

    // ---- Phase B (R6/R14): fp32 gather ----
    const int nb  = nb_sh;
    const int cg  = tid & 63;
    const int sub = tid >> 6;
    const int h   = cg >> 3;
    const __half* base = g_mxh + cg * 8;

    float acc[8] = {0.f, 0.f, 0.f, 0.f, 0.f, 0.f, 0.f, 0.f};
    float den = 0.f;
    int k = sub;
    for (; k + 6 < nb; k += 8) {
        int j0 = ulist[k], j1 = ulist[k + 2], j2 = ulist[k + 4], j3 = ulist[k + 6];
        uint4 r0 = __ldg((const uint4*)(base + (size_t)j0 * CTOT));
        uint4 r1 = __ldg((const uint4*)(base + (size_t)j1 * CTOT));
        uint4 r2 = __ldg((const uint4*)(base + (size_t)j2 * CTOT));
        uint4 r3 = __ldg((const uint4*)(base + (size_t)j3 * CTOT));
        float w0 = wsh[k][h], w1 = wsh[k + 2][h], w2 = wsh[k + 4][h], w3 = wsh[k + 6][h];
        acc8(acc, r0, w0); acc8(acc, r1, w1); acc8(acc, r2, w2); acc8(acc, r3, w3);
        den += w0; den += w1; den += w2; den += w3;
    }
    for (; k < nb; k += 2) {
        int j0 = ulist[k];
        uint4 r0 = __ldg((const uint4*)(base + (size_t)j0 * CTOT));
        float w0 = wsh[k][h];
        acc8(acc, r0, w0);
        den += w0;
    }

    if (sub == 1) {
        #pragma unroll
        for (int q = 0; q < 8; q++) pac[cg][q] = acc[q];
        pden1[cg] = den;
    }
    __syncthreads();
    if (sub == 0) {
        den += pden1[cg];
        float inv = 1.f / den;
        float* op = out + (size_t)i * CTOT + cg * 8;
        *(float4*)(op) = make_float4((acc[0] + pac[cg][0]) * inv,
                                     (acc[1] + pac[cg][1]) * inv,
                                     (acc[2] + pac[cg][2]) * inv,
                                     (acc[3] + pac[cg][3]) * inv);
        *(float4*)(op + 4) = make_float4((acc[4] + pac[cg][4]) * inv,
                                         (acc[5] + pac[cg][5]) * inv,
                                         (acc[6] + pac[cg][6]) * inv,
                                         (acc[7] + pac[cg][7]) * inv);
    }
}

// ---------------------------------------------------------------------------
// Inputs: x[4096,512], adj[4096,4096], W[8,512,64], a_origin[8,64] (cancels),
//         a_dst[8,64].  Output: float32 [4096, 512]
// ---------------------------------------------------------------------------
extern "C" void kernel_launch(void* const* d_in, const int* in_sizes, int n_in,
                              void* d_out, int out_size)
{
    const float* x     = (const float*)d_in[0];
    const float* adj   = (const float*)d_in[1];
    const float* W     = (const float*)d_in[2];
    const float* a_dst = (const float*)d_in[4];
    float* out = (float*)d_out;

    prep_kernel<<<1088, 256>>>(x, W);
    gemm_mx_kernel<<<dim3(64, 4), 256>>>(a_dst);
    aggregate_kernel<<<N_NODES, 128>>>(adj, out);
}